// round 16
// baseline (speedup 1.0000x reference)
#include <cuda_runtime.h>

#define DIN   32
#define H     128
#define TSRC  256
#define TGT   64
#define HP    68          // padded row stride of staged-h smem buffer (floats)
#define NTHR  256
#define NBLK  128

typedef unsigned long long ull;

// ---------------- device-global state ----------------
__device__ float4 g_wE0[160 * 128];
__device__ float4 g_wE1[256 * 128];
__device__ float4 g_wD0[160 * 128];
__device__ float4 g_wD1[256 * 128];
__device__ float4 g_bias[4 * 128];          // set 0..3 = e0,e1,d0,d1 ; (bih+bhh) per gate
__device__ float  g_h0[2][8 * H * 64];      // [slot][bg][j][row]
__device__ float  g_h1[2][8 * H * 64];
__device__ float  g_fb2[2][8 * DIN * 64];   // [slot][bg][m][row] decoder head accumulator
__device__ unsigned g_bar[8 * 32];          // per-bg barrier counters (padded)

// ---------------- fused prep kernel ----------------
__device__ __forceinline__ void pack_one(const float* Wx, const float* Wh,
                                         float4* dst, int KX, int KH, int idx) {
    int k = idx >> 7, j = idx & 127;
    float4 v;
    if (k < KX) {
        v.x = Wx[(0 * H + j) * KX + k];
        v.y = Wx[(1 * H + j) * KX + k];
        v.z = Wx[(2 * H + j) * KX + k];
        v.w = Wx[(3 * H + j) * KX + k];
    } else {
        int kk = k - KX;
        v.x = Wh[(0 * H + j) * KH + kk];
        v.y = Wh[(1 * H + j) * KH + kk];
        v.z = Wh[(2 * H + j) * KH + kk];
        v.w = Wh[(3 * H + j) * KH + kk];
    }
    dst[idx] = v;
}

__global__ void prep(const float* eW0, const float* eU0, const float* eW1, const float* eU1,
                     const float* dW0, const float* dU0, const float* dW1, const float* dU1,
                     const float* ebi0, const float* ebh0, const float* ebi1, const float* ebh1,
                     const float* dbi0, const float* dbh0, const float* dbi1, const float* dbh1) {
    int i = blockIdx.x * blockDim.x + threadIdx.x;
    if (i < 20480)            pack_one(eW0, eU0, g_wE0, DIN, H, i);
    else if (i < 53248)       pack_one(eW1, eU1, g_wE1, H,   H, i - 20480);
    else if (i < 73728)       pack_one(dW0, dU0, g_wD0, DIN, H, i - 53248);
    else if (i < 106496)      pack_one(dW1, dU1, g_wD1, H,   H, i - 73728);
    else if (i < 107008) {
        int r = i - 106496, set = r >> 7, j = r & 127;
        const float* bi = (set == 0) ? ebi0 : (set == 1) ? ebi1 : (set == 2) ? dbi0 : dbi1;
        const float* bh = (set == 0) ? ebh0 : (set == 1) ? ebh1 : (set == 2) ? dbh0 : dbh1;
        g_bias[set * 128 + j] = make_float4(bi[0 * H + j] + bh[0 * H + j],
                                            bi[1 * H + j] + bh[1 * H + j],
                                            bi[2 * H + j] + bh[2 * H + j],
                                            bi[3 * H + j] + bh[3 * H + j]);
    } else if (i < 107264) {
        g_bar[i - 107008] = 0u;
    }
}

// ---------------- packed f32x2 helpers ----------------
__device__ __forceinline__ void ffma2(ull& d, ull a, ull b) {
    asm("fma.rn.f32x2 %0, %1, %2, %0;" : "+l"(d) : "l"(a), "l"(b));
}
__device__ __forceinline__ ull dup2(float v) {
    ull r; asm("mov.b64 %0, {%1, %1};" : "=l"(r) : "f"(v)); return r;
}
__device__ __forceinline__ float2 up2(ull v) {
    float2 r; asm("mov.b64 {%0, %1}, %2;" : "=f"(r.x), "=f"(r.y) : "l"(v)); return r;
}

// ---------------- activations ----------------
__device__ __forceinline__ float sigf(float x) { return __fdividef(1.f, 1.f + __expf(-x)); }
__device__ __forceinline__ float tnh(float x)  { return __fdividef(2.f, 1.f + __expf(-2.f * x)) - 1.f; }
__device__ __forceinline__ float cellf(float2 if_, float2 go_, float& c) {
    float i = sigf(if_.x), f = sigf(if_.y), g = tnh(go_.x), o = sigf(go_.y);
    c = f * c + i * g;
    return o * tnh(c);
}

// ---------------- staging helpers (256 threads) ----------------
__device__ __forceinline__ void stage_x(const float* x, float* hb, int rbase, int t, int tid) {
    int row = tid >> 2, kq = tid & 3;
    #pragma unroll
    for (int half = 0; half < 2; half++) {
        int k0 = (kq + 4 * half) * 4;
        float4 v = *(const float4*)(x + (size_t)(rbase + row) * (TSRC * DIN) + t * DIN + k0);
        hb[(k0 + 0) * HP + row] = v.x;
        hb[(k0 + 1) * HP + row] = v.y;
        hb[(k0 + 2) * HP + row] = v.z;
        hb[(k0 + 3) * HP + row] = v.w;
    }
}

__device__ __forceinline__ void stage_h(const float* src, float* hb, int koff, int tid) {
    int j = tid >> 1, half = tid & 1;
    const float* s = src + j * 64 + half * 32;
    float* d = hb + (koff + j) * HP + half * 32;
    #pragma unroll
    for (int it = 0; it < 8; it++) {
        float4 v = __ldcg((const float4*)(s + it * 4));
        *(float4*)(d + it * 4) = v;
    }
}

__device__ __forceinline__ void stage_fb(const float* src, float* hb, int tid) {
    #pragma unroll
    for (int s2 = 0; s2 < 2; s2++) {
        int idx4 = tid * 2 + s2;
        int m = idx4 >> 4, off = (idx4 & 15) * 4;
        float4 v = __ldcg((const float4*)(src + m * 64 + off));
        *(float4*)(hb + m * HP + off) = v;
    }
}

// ---------------- per-bg barrier (16 blocks), release/acquire ----------------
__device__ __forceinline__ void bg_barrier(int bg, unsigned target) {
    __syncthreads();
    if (threadIdx.x == 0) {
        unsigned* ctr = &g_bar[bg * 32];
        asm volatile("red.release.gpu.global.add.u32 [%0], %1;"
                     :: "l"(ctr), "r"(1u) : "memory");
        unsigned v;
        do {
            asm volatile("ld.acquire.gpu.global.u32 %0, [%1];"
                         : "=r"(v) : "l"(ctr) : "memory");
            if (v >= target) break;
            __nanosleep(32);
        } while (true);
    }
    __syncthreads();
}

// ---------------- k-sliced accumulate: thread = 4 rows x 2 cols, 4 k-slices ----------------
// Scratch layout (transposed, conflict-free): scr2[i2][t], i2 = c*4 + r_in,
// value = ulonglong2( IF-acc, GO-acc ) for (col 2cp+c, row 4rq+r_in).
template<int K>
__device__ __forceinline__ void do_accum(const float4* __restrict__ sw,
                                         const float* __restrict__ hb,
                                         int slice, int rq4, int cp,
                                         ulonglong2* __restrict__ scr2, int t) {
    ull aIF0[4], aGO0[4], aIF1[4], aGO1[4];
    #pragma unroll
    for (int r = 0; r < 4; r++) { aIF0[r] = 0; aGO0[r] = 0; aIF1[r] = 0; aGO1[r] = 0; }
    const int k0 = slice * (K / 4);
    #pragma unroll 4
    for (int kk = 0; kk < K / 4; kk++) {
        int k = k0 + kk;
        ulonglong2 w0 = *(const ulonglong2*)(sw + k * 8 + 2 * cp);      // col 2cp  : (IF)(GO)
        ulonglong2 w1 = *(const ulonglong2*)(sw + k * 8 + 2 * cp + 1);  // col 2cp+1
        float4 hv = *(const float4*)(hb + k * HP + rq4);                // rows 4rq..4rq+3
        ull d0 = dup2(hv.x), d1 = dup2(hv.y), d2 = dup2(hv.z), d3 = dup2(hv.w);
        ffma2(aIF0[0], w0.x, d0); ffma2(aGO0[0], w0.y, d0);
        ffma2(aIF1[0], w1.x, d0); ffma2(aGO1[0], w1.y, d0);
        ffma2(aIF0[1], w0.x, d1); ffma2(aGO0[1], w0.y, d1);
        ffma2(aIF1[1], w1.x, d1); ffma2(aGO1[1], w1.y, d1);
        ffma2(aIF0[2], w0.x, d2); ffma2(aGO0[2], w0.y, d2);
        ffma2(aIF1[2], w1.x, d2); ffma2(aGO1[2], w1.y, d2);
        ffma2(aIF0[3], w0.x, d3); ffma2(aGO0[3], w0.y, d3);
        ffma2(aIF1[3], w1.x, d3); ffma2(aGO1[3], w1.y, d3);
    }
    #pragma unroll
    for (int r = 0; r < 4; r++) {
        scr2[(0 * 4 + r) * NTHR + t] = make_ulonglong2(aIF0[r], aGO0[r]);
        scr2[(1 * 4 + r) * NTHR + t] = make_ulonglong2(aIF1[r], aGO1[r]);
    }
}

// ---------------- reduce 4 slices + bias + cell + store (owner threads tid<128) ----------------
__device__ __forceinline__ void finalize_cell(const ulonglong2* __restrict__ scr2,
                                              const float4* __restrict__ sb_set,
                                              int rp, int cp, float* cs,
                                              float* gdst, int colbase, float* h1loc) {
    const int tp_base = (cp >> 1) * 32 + (cp & 1) * 16 + (rp >> 1);
    const int rin0 = 2 * (rp & 1);
    float2 V[8];
    #pragma unroll
    for (int i = 0; i < 8; i++) V[i] = make_float2(0.f, 0.f);
    #pragma unroll
    for (int s = 0; s < 4; s++) {
        int tp = s * 64 + tp_base;
        #pragma unroll
        for (int c = 0; c < 2; c++) {
            #pragma unroll
            for (int dr = 0; dr < 2; dr++) {
                ulonglong2 qv = scr2[(c * 4 + rin0 + dr) * NTHR + tp];
                float2 fi = up2(qv.x), fg = up2(qv.y);
                V[c * 4 + dr * 2 + 0].x += fi.x; V[c * 4 + dr * 2 + 0].y += fi.y;
                V[c * 4 + dr * 2 + 1].x += fg.x; V[c * 4 + dr * 2 + 1].y += fg.y;
            }
        }
    }
    #pragma unroll
    for (int c = 0; c < 2; c++) {
        float4 b = sb_set[2 * cp + c];
        float2 IF0 = make_float2(V[c * 4 + 0].x + b.x, V[c * 4 + 0].y + b.y);
        float2 GO0 = make_float2(V[c * 4 + 1].x + b.z, V[c * 4 + 1].y + b.w);
        float h0v = cellf(IF0, GO0, cs[c * 2 + 0]);
        float2 IF1 = make_float2(V[c * 4 + 2].x + b.x, V[c * 4 + 2].y + b.y);
        float2 GO1 = make_float2(V[c * 4 + 3].x + b.z, V[c * 4 + 3].y + b.w);
        float h1v = cellf(IF1, GO1, cs[c * 2 + 1]);
        int j = colbase + 2 * cp + c;
        __stcg((float2*)(gdst + j * 64 + 2 * rp), make_float2(h0v, h1v));
        if (h1loc) {
            h1loc[(2 * cp + c) * 68 + 2 * rp] = h0v;
            h1loc[(2 * cp + c) * 68 + 2 * rp + 1] = h1v;
        }
    }
}

// ---------------- main persistent kernel ----------------
__global__ void __launch_bounds__(NTHR, 1)
lstm_main(const float* __restrict__ x, const float* __restrict__ linW,
          const float* __restrict__ linb, float* __restrict__ out) {
    extern __shared__ float smf[];
    float4* swE0 = (float4*)smf;             // 1280 f4
    float4* swE1 = swE0 + 1280;              // 2048 f4
    float4* swD0 = swE1 + 2048;              // 1280 f4
    float4* swD1 = swD0 + 1280;              // 2048 f4
    float4* sb   = swD1 + 2048;              // 32 f4
    float*  slin2 = (float*)(sb + 32);       // [32 m][8 local j]
    float*  slnb32 = slin2 + 256;            // 32
    float*  h1loc  = slnb32 + 32;            // [8 cl][68] = 544
    float*  hbuf   = h1loc + 544;            // 288*HP floats
    ulonglong2* scr2 = (ulonglong2*)(hbuf + 288 * HP);   // [8][256] ulonglong2 = 32KB

    const int tid = threadIdx.x;
    const int bg = blockIdx.x >> 4, cg = blockIdx.x & 15;
    const int rbase = bg * 64;
    const int lane = tid & 31, w = tid >> 5;
    const int slice = w >> 1;                        // 0..3
    const int cp_a = 2 * (w & 1) + (lane >> 4);      // producer colpair 0..3
    const int rq4 = 4 * (lane & 15);                 // producer row base 0..60
    // owner mapping (tid<128): identical to R15
    const int rp = 16 * ((tid >> 5) & 1) + (lane & 15);
    const int cp_o = 2 * ((tid >> 6) & 1) + (lane >> 4);
    const int col0 = cg * 8;

    // load weight slices / bias / lin into smem (once)
    for (int i = tid; i < 1280; i += NTHR) swE0[i] = g_wE0[(i >> 3) * 128 + col0 + (i & 7)];
    for (int i = tid; i < 2048; i += NTHR) swE1[i] = g_wE1[(i >> 3) * 128 + col0 + (i & 7)];
    for (int i = tid; i < 1280; i += NTHR) swD0[i] = g_wD0[(i >> 3) * 128 + col0 + (i & 7)];
    for (int i = tid; i < 2048; i += NTHR) swD1[i] = g_wD1[(i >> 3) * 128 + col0 + (i & 7)];
    if (tid < 32) sb[tid] = g_bias[(tid >> 3) * 128 + col0 + (tid & 7)];
    if (tid < 256) slin2[tid] = linW[(tid >> 3) * H + col0 + (tid & 7)];   // [m][cl]
    if (tid < 32) slnb32[tid] = linb[tid];
    for (int i = tid; i < 288 * HP; i += NTHR) hbuf[i] = 0.f;
    __syncthreads();

    float cs0[4] = {0.f, 0.f, 0.f, 0.f};   // layer-0 cell state (owners tid<128)
    float cs1[4] = {0.f, 0.f, 0.f, 0.f};   // layer-1 cell state
    unsigned nbar = 0;

    // ============ encoder: phase p computes layer0(p) and layer1(p-1) ============
    for (int p = 0; p <= TSRC; p++) {
        if (p < TSRC) stage_x(x, hbuf, rbase, p, tid);
        if (p >= 1) stage_h(g_h0[(p - 1) & 1] + bg * 8192, hbuf, 32, tid);   // h0(p-1)
        if (p >= 2) stage_h(g_h1[p & 1] + bg * 8192, hbuf, 160, tid);        // h1(p-2)
        __syncthreads();
        if (p < TSRC) {
            do_accum<160>(swE0, hbuf, slice, rq4, cp_a, scr2, tid);
            __syncthreads();
            if (tid < 128)
                finalize_cell(scr2, sb + 0 * 8, rp, cp_o, cs0,
                              g_h0[p & 1] + bg * 8192, col0, nullptr);
            __syncthreads();
        }
        if (p >= 1) {
            do_accum<256>(swE1, hbuf + 32 * HP, slice, rq4, cp_a, scr2, tid);
            __syncthreads();
            if (tid < 128)
                finalize_cell(scr2, sb + 1 * 8, rp, cp_o, cs1,
                              g_h1[(p - 1) & 1] + bg * 8192, col0, nullptr);
        }
        nbar++; bg_barrier(bg, nbar * 16);
    }

    // ============ decoder: 2 phases per step ============
    const int orow = tid & 63, om0 = tid >> 6;     // 4 m-groups x 64 rows
    for (int tt = 0; tt < TGT; tt++) {
        // ---- phase A: layer0 (+ fb init, + out write for tt-1) ----
        if (tt == 0) {
            stage_x(x, hbuf, rbase, TSRC - 1, tid);          // dec_in0 = x[:, -1, :]
        } else {
            const float* fbsrc = g_fb2[(tt + 1) & 1] + bg * 2048;   // slot (tt-1)&1
            stage_fb(fbsrc, hbuf, tid);
            if (cg == 0) {
                #pragma unroll
                for (int u = 0; u < 8; u++) {
                    int m = om0 * 8 + u;
                    float v = __ldcg(fbsrc + m * 64 + orow);
                    out[(size_t)(rbase + orow) * (TGT * DIN) + (tt - 1) * DIN + m] = v;
                }
            }
        }
        if (cg == 0) {
            #pragma unroll
            for (int u = 0; u < 8; u++) {
                int m = om0 * 8 + u;
                __stcg(&g_fb2[tt & 1][bg * 2048 + m * 64 + orow], slnb32[m]);
            }
        }
        stage_h(g_h0[(tt + 1) & 1] + bg * 8192, hbuf, 32, tid);     // h0 prev
        __syncthreads();
        do_accum<160>(swD0, hbuf, slice, rq4, cp_a, scr2, tid);
        __syncthreads();
        if (tid < 128)
            finalize_cell(scr2, sb + 2 * 8, rp, cp_o, cs0,
                          g_h0[tt & 1] + bg * 8192, col0, nullptr);
        nbar++; bg_barrier(bg, nbar * 16);

        // ---- phase B: layer1 + head partial (atomic accumulate) ----
        stage_h(g_h0[tt & 1] + bg * 8192, hbuf, 32, tid);           // h0(tt) fresh
        stage_h(g_h1[(tt + 1) & 1] + bg * 8192, hbuf, 160, tid);    // h1 prev
        __syncthreads();
        do_accum<256>(swD1, hbuf + 32 * HP, slice, rq4, cp_a, scr2, tid);
        __syncthreads();
        if (tid < 128)
            finalize_cell(scr2, sb + 3 * 8, rp, cp_o, cs1,
                          g_h1[tt & 1] + bg * 8192, col0, h1loc);
        __syncthreads();
        {
            #pragma unroll
            for (int u = 0; u < 8; u++) {
                int m = om0 * 8 + u;
                float acc = 0.f;
                #pragma unroll
                for (int j2 = 0; j2 < 8; j2++)
                    acc += h1loc[j2 * 68 + orow] * slin2[m * 8 + j2];
                atomicAdd(&g_fb2[tt & 1][bg * 2048 + m * 64 + orow], acc);
            }
        }
        nbar++; bg_barrier(bg, nbar * 16);
    }

    // ---- epilogue: write out[:, TGT-1, :] ----
    if (cg == 0) {
        const float* fbsrc = g_fb2[(TGT - 1) & 1] + bg * 2048;
        #pragma unroll
        for (int u = 0; u < 8; u++) {
            int m = om0 * 8 + u;
            float v = __ldcg(fbsrc + m * 64 + orow);
            out[(size_t)(rbase + orow) * (TGT * DIN) + (TGT - 1) * DIN + m] = v;
        }
    }
}

// ---------------- host entry ----------------
extern "C" void kernel_launch(void* const* d_in, const int* in_sizes, int n_in,
                              void* d_out, int out_size) {
    const float* x    = (const float*)d_in[0];
    const float* eW0  = (const float*)d_in[2];
    const float* eU0  = (const float*)d_in[3];
    const float* ebi0 = (const float*)d_in[4];
    const float* ebh0 = (const float*)d_in[5];
    const float* eW1  = (const float*)d_in[6];
    const float* eU1  = (const float*)d_in[7];
    const float* ebi1 = (const float*)d_in[8];
    const float* ebh1 = (const float*)d_in[9];
    const float* dW0  = (const float*)d_in[10];
    const float* dU0  = (const float*)d_in[11];
    const float* dbi0 = (const float*)d_in[12];
    const float* dbh0 = (const float*)d_in[13];
    const float* dW1  = (const float*)d_in[14];
    const float* dU1  = (const float*)d_in[15];
    const float* dbi1 = (const float*)d_in[16];
    const float* dbh1 = (const float*)d_in[17];
    const float* linW = (const float*)d_in[18];
    const float* linb = (const float*)d_in[19];

    static const int SMEM_BYTES = (1280 + 2048 + 1280 + 2048 + 32) * 16
                                  + (256 + 32 + 544) * 4 + 288 * HP * 4
                                  + 32768;          // 221440 B
    cudaFuncSetAttribute(lstm_main, cudaFuncAttributeMaxDynamicSharedMemorySize, SMEM_BYTES);

    prep<<<(107264 + 255) / 256, 256>>>(eW0, eU0, eW1, eU1, dW0, dU0, dW1, dU1,
                                        ebi0, ebh0, ebi1, ebh1, dbi0, dbh0, dbi1, dbh1);
    lstm_main<<<NBLK, NTHR, SMEM_BYTES>>>(x, linW, linb, (float*)d_out);
}